// round 1
// baseline (speedup 1.0000x reference)
#include <cuda_runtime.h>
#include <math.h>

#define DET 512
#define NB  16
#define NT  180

// scratch: filtered sinogram, layout [b][t][d] (d contiguous)
static __device__ float g_xf[(size_t)NB * NT * DET];

// ---------------------------------------------------------------------------
// Kernel 1: Ram-Lak filtering as direct convolution with closed-form kernel.
//   xf[b,t,d] = 0.5*x[b,d,t] + sum_{m: (d-m) odd} x[b,m,t] * (-2/(pi*(d-m))^2)
// Block: one batch b, tile of 16 angles t. 512 threads, thread = output d.
// ---------------------------------------------------------------------------
__global__ __launch_bounds__(512) void filter_kernel(const float* __restrict__ x)
{
    const int b  = blockIdx.x;
    const int t0 = blockIdx.y * 16;
    const int tid = threadIdx.x;            // 0..511

    __shared__ __align__(16) float xs[DET][16];   // x[b][m][t0..t0+15]
    __shared__ float Gt[DET];

    // build kernel table
    {
        int k = tid;
        float v;
        if (k == 0)       v = 0.5f;
        else if (k & 1) { float fk = (float)k; v = -2.0f / (9.869604401089358f * fk * fk); }
        else              v = 0.0f;
        Gt[k] = v;
    }

    // load x tile (transpose gather): element (m, tt) = x[b][m][t0+tt]
    const float* xb = x + (size_t)b * DET * NT;
    const int tt = tid & 15;
    const int mb = tid >> 4;                 // 0..31
    const int tg0 = t0 + tt;
    #pragma unroll
    for (int p = 0; p < 16; p++) {
        int m = mb + p * 32;
        xs[m][tt] = (tg0 < NT) ? xb[m * NT + tg0] : 0.0f;
    }
    __syncthreads();

    const int d = tid;
    float4 acc[4];
    {
        const float4* xd = (const float4*)xs[d];
        #pragma unroll
        for (int q = 0; q < 4; q++) {
            float4 v = xd[q];
            acc[q].x = 0.5f * v.x; acc[q].y = 0.5f * v.y;
            acc[q].z = 0.5f * v.z; acc[q].w = 0.5f * v.w;
        }
    }

    const int m0 = (d & 1) ^ 1;              // opposite parity of d
    for (int j = 0; j < 256; j++) {
        int m = m0 + 2 * j;
        int k = d - m; k = (k < 0) ? -k : k;
        float gv = Gt[k];
        const float4* xm = (const float4*)xs[m];
        #pragma unroll
        for (int q = 0; q < 4; q++) {
            float4 v = xm[q];
            acc[q].x = fmaf(gv, v.x, acc[q].x);
            acc[q].y = fmaf(gv, v.y, acc[q].y);
            acc[q].z = fmaf(gv, v.z, acc[q].z);
            acc[q].w = fmaf(gv, v.w, acc[q].w);
        }
    }

    // store xf[b][t][d]
    float vals[16];
    #pragma unroll
    for (int q = 0; q < 4; q++) {
        vals[q*4+0] = acc[q].x; vals[q*4+1] = acc[q].y;
        vals[q*4+2] = acc[q].z; vals[q*4+3] = acc[q].w;
    }
    #pragma unroll
    for (int r = 0; r < 16; r++) {
        int tg = t0 + r;
        if (tg < NT) g_xf[((size_t)b * NT + tg) * DET + d] = vals[r];
    }
}

// ---------------------------------------------------------------------------
// Kernel 2: backprojection. 64x64 pixel tile per block, 256 threads,
// 16 pixels/thread (y-strided by 4). Zero-padded smem column (no masks),
// double-buffered, 1 sync per angle.
// ---------------------------------------------------------------------------
__global__ __launch_bounds__(256) void backproj_kernel(float* __restrict__ out)
{
    const int b  = blockIdx.z;
    const int x0 = blockIdx.x * 64;
    const int y0 = blockIdx.y * 64;
    const int tid = threadIdx.x;             // 0..255
    const int tx = tid & 63;
    const int ty = tid >> 6;                 // 0..3

    __shared__ __align__(16) float col[2][768];   // pad 128 each side, zeros
    __shared__ float2 cs[NT];

    // zero pad regions (written once; loads never touch them)
    if (tid < 128) { col[0][tid] = 0.0f; col[1][tid] = 0.0f; }
    else { int i = tid - 128 + 640; col[0][i] = 0.0f; col[1][i] = 0.0f; }

    if (tid < NT) {
        float rad = (float)tid * 0.017453292519943295f;
        float sv, cv;
        sincosf(rad, &sv, &cv);
        cs[tid] = make_float2(cv, sv);
    }

    const float* xfb = g_xf + (size_t)b * NT * DET;

    // preload angle 0
    {
        float2 v = ((const float2*)xfb)[tid];
        ((float2*)(col[0] + 128))[tid] = v;
    }
    __syncthreads();

    float acc[16];
    #pragma unroll
    for (int k = 0; k < 16; k++) acc[k] = 0.0f;

    const float fx = (float)(x0 + tx) - 255.5f;
    const float fy = (float)(y0 + ty) - 255.5f;
    const float lim = 65408.0f;              // (1 - 1/512) * 256^2

    // does any of this thread's 16 pixels lie inside the circle?
    float fymin;
    {
        float lo = fy, hi = fy + 60.0f;
        fymin = (lo <= 0.0f && hi >= 0.0f) ? 0.0f : fminf(fabsf(lo), fabsf(hi));
    }
    const bool anyvalid = (fx * fx + fymin * fymin) <= lim;
    const bool warp_active = __any_sync(0xffffffffu, anyvalid);

    for (int t = 0; t < NT; t++) {
        const int cur = t & 1;
        if (t + 1 < NT) {
            float2 v = ((const float2*)(xfb + (size_t)(t + 1) * DET))[tid];
            ((float2*)(col[cur ^ 1] + 128))[tid] = v;
        }
        if (warp_active) {
            const float c = cs[t].x, s = cs[t].y;
            // iy = c*(x-255.5) - s*(y-255.5) + 255.5, plus +128 pad offset
            float iy = fmaf(c, fx, fmaf(-s, fy, 383.5f));
            const float s4 = 4.0f * s;
            const float* cp = col[cur];
            #pragma unroll
            for (int k = 0; k < 16; k++) {
                float fl = floorf(iy);
                float w  = iy - fl;
                int   i0 = (int)fl;
                float g0 = cp[i0];
                float g1 = cp[i0 + 1];
                acc[k] += g0 + w * (g1 - g0);
                iy -= s4;
            }
        }
        __syncthreads();
    }

    // epilogue: circle mask + pi/(2*180) scale
    const float scale = 0.008726646259971648f;   // pi/360
    float* ob = out + (size_t)b * DET * DET;
    #pragma unroll
    for (int k = 0; k < 16; k++) {
        int   py  = y0 + ty + 4 * k;
        float fyk = fy + 4.0f * (float)k;
        float m   = ((fx * fx + fyk * fyk) <= lim) ? 1.0f : 0.0f;
        ob[(size_t)py * DET + (x0 + tx)] = acc[k] * m * scale;
    }
}

extern "C" void kernel_launch(void* const* d_in, const int* in_sizes, int n_in,
                              void* d_out, int out_size)
{
    const float* x = (const float*)d_in[0];
    float* out = (float*)d_out;

    dim3 gf(NB, 12);          // 16 batches x ceil(180/16) angle tiles
    filter_kernel<<<gf, 512>>>(x);

    dim3 gb(8, 8, NB);        // 8x8 tiles of 64x64 pixels, per batch
    backproj_kernel<<<gb, 256>>>(out);
}

// round 2
// speedup vs baseline: 1.2219x; 1.2219x over previous
#include <cuda_runtime.h>
#include <math.h>

#define DET 512
#define NB  16
#define NT  180

// scratch: filtered sinogram, layout [b][t][d] (d contiguous).
// One extra padding column per batch so the backproj prefetch of column t+1
// is unconditional (value never consumed for t = NT-1).
static __device__ float g_xf[(size_t)NB * (NT + 1) * DET];

// ---------------------------------------------------------------------------
// Kernel 1: Ram-Lak filtering as direct convolution with closed-form kernel.
//   xf[b,t,d] = 0.5*x[b,d,t] + sum_{m: (d-m) odd} x[b,m,t] * (-2/(pi*(d-m))^2)
// Block: one batch b, tile of 16 angles t. 512 threads, thread = output d.
// ---------------------------------------------------------------------------
__global__ __launch_bounds__(512) void filter_kernel(const float* __restrict__ x)
{
    const int b  = blockIdx.x;
    const int t0 = blockIdx.y * 16;
    const int tid = threadIdx.x;            // 0..511

    __shared__ __align__(16) float xs[DET][16];   // x[b][m][t0..t0+15]
    __shared__ float Gt[DET];

    // build kernel table
    {
        int k = tid;
        float v;
        if (k == 0)       v = 0.5f;
        else if (k & 1) { float fk = (float)k; v = -2.0f / (9.869604401089358f * fk * fk); }
        else              v = 0.0f;
        Gt[k] = v;
    }

    // load x tile (transpose gather): element (m, tt) = x[b][m][t0+tt]
    const float* xb = x + (size_t)b * DET * NT;
    const int tt = tid & 15;
    const int mb = tid >> 4;                 // 0..31
    const int tg0 = t0 + tt;
    #pragma unroll
    for (int p = 0; p < 16; p++) {
        int m = mb + p * 32;
        xs[m][tt] = (tg0 < NT) ? xb[m * NT + tg0] : 0.0f;
    }
    __syncthreads();

    const int d = tid;
    float4 acc[4];
    {
        const float4* xd = (const float4*)xs[d];
        #pragma unroll
        for (int q = 0; q < 4; q++) {
            float4 v = xd[q];
            acc[q].x = 0.5f * v.x; acc[q].y = 0.5f * v.y;
            acc[q].z = 0.5f * v.z; acc[q].w = 0.5f * v.w;
        }
    }

    const int m0 = (d & 1) ^ 1;              // opposite parity of d
    for (int j = 0; j < 256; j++) {
        int m = m0 + 2 * j;
        int k = d - m; k = (k < 0) ? -k : k;
        float gv = Gt[k];
        const float4* xm = (const float4*)xs[m];
        #pragma unroll
        for (int q = 0; q < 4; q++) {
            float4 v = xm[q];
            acc[q].x = fmaf(gv, v.x, acc[q].x);
            acc[q].y = fmaf(gv, v.y, acc[q].y);
            acc[q].z = fmaf(gv, v.z, acc[q].z);
            acc[q].w = fmaf(gv, v.w, acc[q].w);
        }
    }

    // store xf[b][t][d]
    float vals[16];
    #pragma unroll
    for (int q = 0; q < 4; q++) {
        vals[q*4+0] = acc[q].x; vals[q*4+1] = acc[q].y;
        vals[q*4+2] = acc[q].z; vals[q*4+3] = acc[q].w;
    }
    #pragma unroll
    for (int r = 0; r < 16; r++) {
        int tg = t0 + r;
        if (tg < NT) g_xf[((size_t)b * (NT + 1) + tg) * DET + d] = vals[r];
    }
}

// ---------------------------------------------------------------------------
// Kernel 2: backprojection. 64x64 pixel tile per block, 256 threads,
// 16 pixels/thread (y-strided by 4). Zero-padded smem column (no masks),
// double-buffered, 1 sync per angle.
// __launch_bounds__(256, 8): cap regs at 32 so all 1024 blocks are resident
// in a single wave (<= 7 blocks/SM needed on 148 SMs).
// ---------------------------------------------------------------------------
__global__ __launch_bounds__(256, 8) void backproj_kernel(float* __restrict__ out)
{
    const int b  = blockIdx.z;
    const int x0 = blockIdx.x * 64;
    const int y0 = blockIdx.y * 64;
    const int tid = threadIdx.x;             // 0..255
    const int tx = tid & 63;
    const int ty = tid >> 6;                 // 0..3

    __shared__ __align__(16) float col[2][768];   // pad 128 each side, zeros
    __shared__ float2 cs[NT];

    // zero pad regions (written once; loads never touch them)
    if (tid < 128) { col[0][tid] = 0.0f; col[1][tid] = 0.0f; }
    else { int i = tid - 128 + 640; col[0][i] = 0.0f; col[1][i] = 0.0f; }

    if (tid < NT) {
        float rad = (float)tid * 0.017453292519943295f;
        float sv, cv;
        sincosf(rad, &sv, &cv);
        cs[tid] = make_float2(cv, sv);
    }

    const float* xfb = g_xf + (size_t)b * (NT + 1) * DET;

    // preload angle 0
    {
        float2 v = ((const float2*)xfb)[tid];
        ((float2*)(col[0] + 128))[tid] = v;
    }
    __syncthreads();

    float acc[16];
    #pragma unroll
    for (int k = 0; k < 16; k++) acc[k] = 0.0f;

    const float fx = (float)(x0 + tx) - 255.5f;
    const float fy = (float)(y0 + ty) - 255.5f;
    const float lim = 65408.0f;              // (1 - 1/512) * 256^2

    // does any of this thread's 16 pixels lie inside the circle?
    float fymin;
    {
        float lo = fy, hi = fy + 60.0f;
        fymin = (lo <= 0.0f && hi >= 0.0f) ? 0.0f : fminf(fabsf(lo), fabsf(hi));
    }
    const bool anyvalid = (fx * fx + fymin * fymin) <= lim;
    const bool warp_active = __any_sync(0xffffffffu, anyvalid);

    for (int t = 0; t < NT; t++) {
        const int cur = t & 1;
        // unconditional prefetch of column t+1 (padding column exists at t=NT)
        {
            float2 v = ((const float2*)(xfb + (size_t)(t + 1) * DET))[tid];
            ((float2*)(col[cur ^ 1] + 128))[tid] = v;
        }
        if (warp_active) {
            const float c = cs[t].x, s = cs[t].y;
            // iy = c*(x-255.5) - s*(y-255.5) + 255.5, plus +128 pad offset
            float iy = fmaf(c, fx, fmaf(-s, fy, 383.5f));
            const float s4 = 4.0f * s;
            const float* cp = col[cur];
            #pragma unroll
            for (int k = 0; k < 16; k++) {
                int   i0 = __float2int_rd(iy);
                float fl = (float)i0;
                float w  = iy - fl;
                float g0 = cp[i0];
                float g1 = cp[i0 + 1];
                acc[k] += g0 + w * (g1 - g0);
                iy -= s4;
            }
        }
        __syncthreads();
    }

    // epilogue: circle mask + pi/(2*180) scale
    const float scale = 0.008726646259971648f;   // pi/360
    float* ob = out + (size_t)b * DET * DET;
    #pragma unroll
    for (int k = 0; k < 16; k++) {
        int   py  = y0 + ty + 4 * k;
        float fyk = fy + 4.0f * (float)k;
        float m   = ((fx * fx + fyk * fyk) <= lim) ? 1.0f : 0.0f;
        ob[(size_t)py * DET + (x0 + tx)] = acc[k] * m * scale;
    }
}

extern "C" void kernel_launch(void* const* d_in, const int* in_sizes, int n_in,
                              void* d_out, int out_size)
{
    const float* x = (const float*)d_in[0];
    float* out = (float*)d_out;

    dim3 gf(NB, 12);          // 16 batches x ceil(180/16) angle tiles
    filter_kernel<<<gf, 512>>>(x);

    dim3 gb(8, 8, NB);        // 8x8 tiles of 64x64 pixels, per batch
    backproj_kernel<<<gb, 256>>>(out);
}

// round 3
// speedup vs baseline: 1.2426x; 1.0169x over previous
#include <cuda_runtime.h>
#include <math.h>

#define DET 512
#define NB  16
#define NT  180

// scratch: filtered sinogram, layout [b][t][d] (d contiguous).
// One extra padding column per batch so the backproj prefetch of column t+1
// is unconditional (value never consumed for t = NT-1).
static __device__ float g_xf[(size_t)NB * (NT + 1) * DET];

// ---------------------------------------------------------------------------
// Kernel 1: Ram-Lak filtering as direct convolution with closed-form kernel.
//   xf[b,t,d] = 0.5*x[b,d,t] + sum_{m: (d-m) odd} x[b,m,t] * (-2/(pi*(d-m))^2)
// ---------------------------------------------------------------------------
__global__ __launch_bounds__(512) void filter_kernel(const float* __restrict__ x)
{
    const int b  = blockIdx.x;
    const int t0 = blockIdx.y * 16;
    const int tid = threadIdx.x;            // 0..511

    __shared__ __align__(16) float xs[DET][16];   // x[b][m][t0..t0+15]
    __shared__ float Gt[DET];

    {
        int k = tid;
        float v;
        if (k == 0)       v = 0.5f;
        else if (k & 1) { float fk = (float)k; v = -2.0f / (9.869604401089358f * fk * fk); }
        else              v = 0.0f;
        Gt[k] = v;
    }

    const float* xb = x + (size_t)b * DET * NT;
    const int tt = tid & 15;
    const int mb = tid >> 4;                 // 0..31
    const int tg0 = t0 + tt;
    #pragma unroll
    for (int p = 0; p < 16; p++) {
        int m = mb + p * 32;
        xs[m][tt] = (tg0 < NT) ? xb[m * NT + tg0] : 0.0f;
    }
    __syncthreads();

    const int d = tid;
    float4 acc[4];
    {
        const float4* xd = (const float4*)xs[d];
        #pragma unroll
        for (int q = 0; q < 4; q++) {
            float4 v = xd[q];
            acc[q].x = 0.5f * v.x; acc[q].y = 0.5f * v.y;
            acc[q].z = 0.5f * v.z; acc[q].w = 0.5f * v.w;
        }
    }

    const int m0 = (d & 1) ^ 1;              // opposite parity of d
    for (int j = 0; j < 256; j++) {
        int m = m0 + 2 * j;
        int k = d - m; k = (k < 0) ? -k : k;
        float gv = Gt[k];
        const float4* xm = (const float4*)xs[m];
        #pragma unroll
        for (int q = 0; q < 4; q++) {
            float4 v = xm[q];
            acc[q].x = fmaf(gv, v.x, acc[q].x);
            acc[q].y = fmaf(gv, v.y, acc[q].y);
            acc[q].z = fmaf(gv, v.z, acc[q].z);
            acc[q].w = fmaf(gv, v.w, acc[q].w);
        }
    }

    float vals[16];
    #pragma unroll
    for (int q = 0; q < 4; q++) {
        vals[q*4+0] = acc[q].x; vals[q*4+1] = acc[q].y;
        vals[q*4+2] = acc[q].z; vals[q*4+3] = acc[q].w;
    }
    #pragma unroll
    for (int r = 0; r < 16; r++) {
        int tg = t0 + r;
        if (tg < NT) g_xf[((size_t)b * (NT + 1) + tg) * DET + d] = vals[r];
    }
}

// ---------------------------------------------------------------------------
// Kernel 2: backprojection, (g, delta) float2 column -> one LDS.64 per tap.
//   col2[i] = (col[i], col[i+1]-col[i]); tap = acc + g + w*delta.
// Pad entries are (0,0); boundary entries -1 and 511 encode the exact
// reference masking (only one valid tap contributes).
// ---------------------------------------------------------------------------
__global__ __launch_bounds__(256, 7) void backproj_kernel(float* __restrict__ out)
{
    const int b  = blockIdx.z;
    const int x0 = blockIdx.x * 64;
    const int y0 = blockIdx.y * 64;
    const int tid = threadIdx.x;             // 0..255
    const int tx = tid & 63;
    const int ty = tid >> 6;                 // 0..3

    // index range used: i0 in [-68, 579]; array covers [-128, 640)
    __shared__ __align__(16) float2 col2[2][768];
    __shared__ float2 cs[NT];

    // zero both buffers (pads included); data region overwritten after sync
    #pragma unroll
    for (int i = tid; i < 768; i += 256) {
        col2[0][i] = make_float2(0.0f, 0.0f);
        col2[1][i] = make_float2(0.0f, 0.0f);
    }

    if (tid < NT) {
        float rad = (float)tid * 0.017453292519943295f;
        float sv, cv;
        sincosf(rad, &sv, &cv);
        cs[tid] = make_float2(cv, sv);
    }
    __syncthreads();

    const float* xfb = g_xf + (size_t)b * (NT + 1) * DET;

    // build buffer 0 from angle 0
    {
        const float* src = xfb;
        float2 v = ((const float2*)src)[tid];
        float  e = (tid < 255) ? src[2 * tid + 2] : 0.0f;
        float4 pk = make_float4(v.x, v.y - v.x, v.y, e - v.y);
        ((float4*)(col2[0] + 128))[tid] = pk;
        if (tid == 0) col2[0][127] = make_float2(0.0f, v.x);   // entry -1
    }
    __syncthreads();

    float acc[16];
    #pragma unroll
    for (int k = 0; k < 16; k++) acc[k] = 0.0f;

    const float fx = (float)(x0 + tx) - 255.5f;
    const float fy = (float)(y0 + ty) - 255.5f;
    const float lim = 65408.0f;              // (1 - 1/512) * 256^2

    float fymin;
    {
        float lo = fy, hi = fy + 60.0f;
        fymin = (lo <= 0.0f && hi >= 0.0f) ? 0.0f : fminf(fabsf(lo), fabsf(hi));
    }
    const bool anyvalid = (fx * fx + fymin * fymin) <= lim;
    const bool warp_active = __any_sync(0xffffffffu, anyvalid);

    for (int t = 0; t < NT; t++) {
        const int cur = t & 1;
        // unconditional prefetch+build of column t+1 into the other buffer
        {
            const float* src = xfb + (size_t)(t + 1) * DET;
            float2 v = ((const float2*)src)[tid];
            float  e = (tid < 255) ? src[2 * tid + 2] : 0.0f;
            float4 pk = make_float4(v.x, v.y - v.x, v.y, e - v.y);
            ((float4*)(col2[cur ^ 1] + 128))[tid] = pk;
            if (tid == 0) col2[cur ^ 1][127] = make_float2(0.0f, v.x);
        }
        if (warp_active) {
            const float c = cs[t].x, s = cs[t].y;
            // iy = c*(x-255.5) - s*(y-255.5) + 255.5, plus +128 pad offset
            float iy = fmaf(c, fx, fmaf(-s, fy, 383.5f));
            const float s4 = 4.0f * s;
            const float2* cp = col2[cur];
            #pragma unroll
            for (int k = 0; k < 16; k++) {
                int    i0 = __float2int_rd(iy);
                float  w  = iy - (float)i0;
                float2 gd = cp[i0];
                acc[k] = fmaf(w, gd.y, acc[k] + gd.x);
                iy -= s4;
            }
        }
        __syncthreads();
    }

    // epilogue: circle mask + pi/(2*180) scale
    const float scale = 0.008726646259971648f;   // pi/360
    float* ob = out + (size_t)b * DET * DET;
    #pragma unroll
    for (int k = 0; k < 16; k++) {
        int   py  = y0 + ty + 4 * k;
        float fyk = fy + 4.0f * (float)k;
        float m   = ((fx * fx + fyk * fyk) <= lim) ? 1.0f : 0.0f;
        ob[(size_t)py * DET + (x0 + tx)] = acc[k] * m * scale;
    }
}

extern "C" void kernel_launch(void* const* d_in, const int* in_sizes, int n_in,
                              void* d_out, int out_size)
{
    const float* x = (const float*)d_in[0];
    float* out = (float*)d_out;

    dim3 gf(NB, 12);          // 16 batches x ceil(180/16) angle tiles
    filter_kernel<<<gf, 512>>>(x);

    dim3 gb(8, 8, NB);        // 8x8 tiles of 64x64 pixels, per batch
    backproj_kernel<<<gb, 256>>>(out);
}